// round 6
// baseline (speedup 1.0000x reference)
#include <cuda_runtime.h>
#include <math.h>

// Hyp-MLR: N=4096, C=256, D=128, CURV=1
// out[n,c] = 2*||a_c|| * asinh(dot*lam). Two kernels:
//  1) stats: per-row ||x||^2; per-class ||p||^2, p.a, 1/||a||, 2||a||ln2
//  2) dual GEMM (X.P^T, X.A^T) + fused approx epilogue.
// GEMM uses 32x32 tiles / 64-thread CTAs (1024 blocks) for load balance
// across 148 SMs and ~12 CTAs/SM of latency hiding.

#define N_TOT 4096
#define C_TOT 256
#define D_TOT 128
#define BN 32
#define BC 32
#define KT 32
#define STR 40             // k-major row stride (floats): 16B aligned, low conflict
#define LN2F 0.69314718055994530942f

__device__ float g_x2[N_TOT];
__device__ float g_p2[C_TOT];
__device__ float g_pa[C_TOT];
__device__ float g_ina[C_TOT];
__device__ float g_w2[C_TOT];

__device__ __forceinline__ float fast_rcp(float x) {
    float y; asm("rcp.approx.f32 %0, %1;" : "=f"(y) : "f"(x)); return y;
}
__device__ __forceinline__ float fast_sqrt(float x) {
    float y; asm("sqrt.approx.f32 %0, %1;" : "=f"(y) : "f"(x)); return y;
}
__device__ __forceinline__ float fast_lg2(float x) {
    float y; asm("lg2.approx.f32 %0, %1;" : "=f"(y) : "f"(x)); return y;
}

// ---------------- Kernel 1: stats ----------------
__global__ __launch_bounds__(256) void stats_kernel(
    const float* __restrict__ X,
    const float* __restrict__ A,
    const float* __restrict__ P)
{
    const int lid = threadIdx.x & 31;
    const int g   = blockIdx.x * 8 + (threadIdx.x >> 5);   // warp id 0..1023

    // 4 X rows per warp
    #pragma unroll
    for (int r = 0; r < 4; r++) {
        int row = g * 4 + r;
        float4 v = *(const float4*)&X[(size_t)row * D_TOT + lid * 4];
        float s = v.x * v.x + v.y * v.y + v.z * v.z + v.w * v.w;
        #pragma unroll
        for (int o = 16; o > 0; o >>= 1) s += __shfl_xor_sync(~0u, s, o);
        if (lid == 0) g_x2[row] = s;
    }
    // 1 class per warp for the first 256 warps
    if (g < C_TOT) {
        float4 p = *(const float4*)&P[(size_t)g * D_TOT + lid * 4];
        float4 a = *(const float4*)&A[(size_t)g * D_TOT + lid * 4];
        float sp  = p.x * p.x + p.y * p.y + p.z * p.z + p.w * p.w;
        float sa  = a.x * a.x + a.y * a.y + a.z * a.z + a.w * a.w;
        float spa = p.x * a.x + p.y * a.y + p.z * a.z + p.w * a.w;
        #pragma unroll
        for (int o = 16; o > 0; o >>= 1) {
            sp  += __shfl_xor_sync(~0u, sp,  o);
            sa  += __shfl_xor_sync(~0u, sa,  o);
            spa += __shfl_xor_sync(~0u, spa, o);
        }
        if (lid == 0) {
            g_p2[g] = sp;
            g_pa[g] = spa;
            float na = sqrtf(sa);
            g_ina[g] = fast_rcp(fmaxf(na, 1e-12f));
            g_w2[g]  = 2.0f * na * LN2F;
        }
    }
}

// ---------------- Kernel 2: dual GEMM + epilogue ----------------
__global__ __launch_bounds__(64, 12) void hyp_mlr_kernel(
    const float* __restrict__ X,   // (N, D)
    const float* __restrict__ A,   // (C, D)
    const float* __restrict__ P,   // (C, D)
    float* __restrict__ out)       // (N, C)
{
    __shared__ float Xs[KT][STR];
    __shared__ float Ps[KT][STR];
    __shared__ float As[KT][STR];

    const int tid = threadIdx.x;
    const int tx  = tid & 7;    // c dim (8 threads)
    const int ty  = tid >> 3;   // n dim (8 threads)
    const int n0  = blockIdx.y * BN;
    const int c0  = blockIdx.x * BC;

    float axp[4][4] = {};   // x.p partials
    float axa[4][4] = {};   // x.a partials

    for (int k0 = 0; k0 < D_TOT; k0 += KT) {
        // Fill: 256 float4 per array; transpose to k-major on store.
        #pragma unroll
        for (int r = 0; r < 4; r++) {
            int idx = tid + r * 64;
            int row = idx >> 3;           // 0..31
            int kq  = (idx & 7) * 4;      // 0,4,..,28
            float4 xv = *(const float4*)&X[(size_t)(n0 + row) * D_TOT + k0 + kq];
            float4 pv = *(const float4*)&P[(size_t)(c0 + row) * D_TOT + k0 + kq];
            float4 av = *(const float4*)&A[(size_t)(c0 + row) * D_TOT + k0 + kq];
            Xs[kq + 0][row] = xv.x; Xs[kq + 1][row] = xv.y;
            Xs[kq + 2][row] = xv.z; Xs[kq + 3][row] = xv.w;
            Ps[kq + 0][row] = pv.x; Ps[kq + 1][row] = pv.y;
            Ps[kq + 2][row] = pv.z; Ps[kq + 3][row] = pv.w;
            As[kq + 0][row] = av.x; As[kq + 1][row] = av.y;
            As[kq + 2][row] = av.z; As[kq + 3][row] = av.w;
        }
        __syncthreads();

        #pragma unroll
        for (int k = 0; k < KT; k++) {
            float4 xv = *(const float4*)&Xs[k][ty * 4];
            float4 pv = *(const float4*)&Ps[k][tx * 4];
            float4 av = *(const float4*)&As[k][tx * 4];
            float xr[4] = {xv.x, xv.y, xv.z, xv.w};
            float pr[4] = {pv.x, pv.y, pv.z, pv.w};
            float ar[4] = {av.x, av.y, av.z, av.w};
            #pragma unroll
            for (int i = 0; i < 4; i++)
                #pragma unroll
                for (int j = 0; j < 4; j++) {
                    axp[i][j] = fmaf(xr[i], pr[j], axp[i][j]);
                    axa[i][j] = fmaf(xr[i], ar[j], axa[i][j]);
                }
        }
        __syncthreads();
    }

    // ---- Epilogue: stats from global, fused approx hyperbolic math.
    float4 xx = *(const float4*)&g_x2[n0 + ty * 4];
    float4 pp = *(const float4*)&g_p2[c0 + tx * 4];
    float4 pv = *(const float4*)&g_pa[c0 + tx * 4];
    float4 iv = *(const float4*)&g_ina[c0 + tx * 4];
    float4 wv4 = *(const float4*)&g_w2[c0 + tx * 4];
    float x2v[4]  = {xx.x, xx.y, xx.z, xx.w};
    float p2v[4]  = {pp.x, pp.y, pp.z, pp.w};
    float pav[4]  = {pv.x, pv.y, pv.z, pv.w};
    float inav[4] = {iv.x, iv.y, iv.z, iv.w};
    float wv[4]   = {wv4.x, wv4.y, wv4.z, wv4.w};
    float x2p1[4], bet[4], bet2[4];
    #pragma unroll
    for (int i = 0; i < 4; i++) x2p1[i] = 1.0f + x2v[i];
    #pragma unroll
    for (int j = 0; j < 4; j++) {
        bet[j]  = 1.0f - p2v[j];
        bet2[j] = bet[j] * bet[j];
    }

    #pragma unroll
    for (int i = 0; i < 4; i++) {
        const int n = n0 + ty * 4 + i;
        float res[4];
        #pragma unroll
        for (int j = 0; j < 4; j++) {
            float xp  = axp[i][j];                   // x.p
            float xa  = axa[i][j];                   // x.a
            float txy = -2.0f * xp;                  // 2*xy (xy = mp.x = -xp)
            float alpha = x2p1[i] + txy;             // 1 + 2xy + x2
            float den   = fmaf(p2v[j], x2v[i], 1.0f + txy);
            // s = ||res||^2 * den^2 = a^2 p2 + a*b*2xy + b^2 x2
            float s   = fmaf(alpha, fmaf(alpha, p2v[j], bet[j] * txy),
                             bet2[j] * x2v[i]);
            float num = fmaf(bet[j], xa, -alpha * pav[j]);   // b*xa - a*pa
            float d2ms = fmaf(den, den, -s);                 // den^2 - s
            // dot*lam = 2*den*num / (na * (den^2 - s))
            float arg = 2.0f * den * num * inav[j] * fast_rcp(d2ms);
            float q   = arg + fast_sqrt(fmaf(arg, arg, 1.0f));
            res[j] = wv[j] * fast_lg2(q);            // 2*na*ln2 * log2(q)
        }
        float4 o = {res[0], res[1], res[2], res[3]};
        *(float4*)&out[(size_t)n * C_TOT + c0 + tx * 4] = o;
    }
}

extern "C" void kernel_launch(void* const* d_in, const int* in_sizes, int n_in,
                              void* d_out, int out_size) {
    const float* X = (const float*)d_in[0];   // output_before (N, D)
    const float* A = (const float*)d_in[1];   // a_mlr (C, D)
    const float* P = (const float*)d_in[2];   // p_mlr (C, D)
    float* out = (float*)d_out;               // (N, C)

    stats_kernel<<<128, 256>>>(X, A, P);
    dim3 grid(C_TOT / BC, N_TOT / BN);        // (8, 128) = 1024 blocks
    hyp_mlr_kernel<<<grid, 64>>>(X, A, P, out);
}

// round 7
// speedup vs baseline: 1.1928x; 1.1928x over previous
#include <cuda_runtime.h>
#include <math.h>

// Hyp-MLR: N=4096, C=256, D=128, CURV=1
// out[n,c] = 2*||a_c|| * asinh(dot*lam). Two kernels:
//  1) stats: per-row ||x||^2; per-class ||p||^2, p.a, 1/||a||, 2||a||ln2
//  2) dual GEMM (X.P^T, X.A^T) + fused approx epilogue.
// GEMM: 64x64 tile, 256 threads, 4x4 dual microtile, KT=64 half-D smem
// phases (2 fills only), conflict-free transposing fill (warp spans rows).

#define N_TOT 4096
#define C_TOT 256
#define D_TOT 128
#define BN 64
#define BC 64
#define KT 64
#define STR 68             // k-major row stride in floats (272B, 16B-aligned)
#define SMEM_FLOATS (3 * KT * STR)
#define SMEM_BYTES (SMEM_FLOATS * 4)
#define LN2F 0.69314718055994530942f

__device__ float g_x2[N_TOT];
__device__ float g_p2[C_TOT];
__device__ float g_pa[C_TOT];
__device__ float g_ina[C_TOT];
__device__ float g_w2[C_TOT];

__device__ __forceinline__ float fast_rcp(float x) {
    float y; asm("rcp.approx.f32 %0, %1;" : "=f"(y) : "f"(x)); return y;
}
__device__ __forceinline__ float fast_sqrt(float x) {
    float y; asm("sqrt.approx.f32 %0, %1;" : "=f"(y) : "f"(x)); return y;
}
__device__ __forceinline__ float fast_lg2(float x) {
    float y; asm("lg2.approx.f32 %0, %1;" : "=f"(y) : "f"(x)); return y;
}

// ---------------- Kernel 1: stats ----------------
__global__ __launch_bounds__(256) void stats_kernel(
    const float* __restrict__ X,
    const float* __restrict__ A,
    const float* __restrict__ P)
{
    const int lid = threadIdx.x & 31;
    const int g   = blockIdx.x * 8 + (threadIdx.x >> 5);   // warp id 0..1023

    #pragma unroll
    for (int r = 0; r < 4; r++) {
        int row = g * 4 + r;
        float4 v = *(const float4*)&X[(size_t)row * D_TOT + lid * 4];
        float s = v.x * v.x + v.y * v.y + v.z * v.z + v.w * v.w;
        #pragma unroll
        for (int o = 16; o > 0; o >>= 1) s += __shfl_xor_sync(~0u, s, o);
        if (lid == 0) g_x2[row] = s;
    }
    if (g < C_TOT) {
        float4 p = *(const float4*)&P[(size_t)g * D_TOT + lid * 4];
        float4 a = *(const float4*)&A[(size_t)g * D_TOT + lid * 4];
        float sp  = p.x * p.x + p.y * p.y + p.z * p.z + p.w * p.w;
        float sa  = a.x * a.x + a.y * a.y + a.z * a.z + a.w * a.w;
        float spa = p.x * a.x + p.y * a.y + p.z * a.z + p.w * a.w;
        #pragma unroll
        for (int o = 16; o > 0; o >>= 1) {
            sp  += __shfl_xor_sync(~0u, sp,  o);
            sa  += __shfl_xor_sync(~0u, sa,  o);
            spa += __shfl_xor_sync(~0u, spa, o);
        }
        if (lid == 0) {
            g_p2[g] = sp;
            g_pa[g] = spa;
            float na = sqrtf(sa);
            g_ina[g] = fast_rcp(fmaxf(na, 1e-12f));
            g_w2[g]  = 2.0f * na * LN2F;
        }
    }
}

// ---------------- Kernel 2: dual GEMM + epilogue ----------------
__global__ __launch_bounds__(256, 2) void hyp_mlr_kernel(
    const float* __restrict__ X,   // (N, D)
    const float* __restrict__ A,   // (C, D)
    const float* __restrict__ P,   // (C, D)
    float* __restrict__ out)       // (N, C)
{
    extern __shared__ float smem[];
    float* Xs = smem;                     // [KT][STR] k-major
    float* Ps = smem + KT * STR;
    float* As = smem + 2 * KT * STR;

    const int tid = threadIdx.x;
    const int tx  = tid & 15;   // c dim
    const int ty  = tid >> 4;   // n dim
    const int n0  = blockIdx.y * BN;
    const int c0  = blockIdx.x * BC;

    // Fill mapping: warp spans 32 distinct rows at one k -> conflict-free STS.
    const int frow = tid & 63;          // 0..63
    const int fks  = (tid >> 6) * 16;   // k sub-slab start: 0,16,32,48

    float axp[4][4] = {};   // x.p partials
    float axa[4][4] = {};   // x.a partials

    #pragma unroll
    for (int ph = 0; ph < 2; ph++) {
        if (ph) __syncthreads();          // protect smem reuse across phases
        const int kb = ph * KT;
        // Per array: 4 LDG.128 (row-strided; L2-resident) + 16 scalar STS.
        const float* xg = &X[(size_t)(n0 + frow) * D_TOT + kb + fks];
        const float* pg = &P[(size_t)(c0 + frow) * D_TOT + kb + fks];
        const float* ag = &A[(size_t)(c0 + frow) * D_TOT + kb + fks];
        #pragma unroll
        for (int q = 0; q < 4; q++) {
            float4 xv = *(const float4*)&xg[q * 4];
            float4 pv = *(const float4*)&pg[q * 4];
            float4 av = *(const float4*)&ag[q * 4];
            int k = fks + q * 4;
            Xs[(k + 0) * STR + frow] = xv.x;
            Xs[(k + 1) * STR + frow] = xv.y;
            Xs[(k + 2) * STR + frow] = xv.z;
            Xs[(k + 3) * STR + frow] = xv.w;
            Ps[(k + 0) * STR + frow] = pv.x;
            Ps[(k + 1) * STR + frow] = pv.y;
            Ps[(k + 2) * STR + frow] = pv.z;
            Ps[(k + 3) * STR + frow] = pv.w;
            As[(k + 0) * STR + frow] = av.x;
            As[(k + 1) * STR + frow] = av.y;
            As[(k + 2) * STR + frow] = av.z;
            As[(k + 3) * STR + frow] = av.w;
        }
        __syncthreads();

        #pragma unroll 4
        for (int k = 0; k < KT; k++) {
            float4 xv = *(const float4*)&Xs[k * STR + ty * 4];
            float4 pv = *(const float4*)&Ps[k * STR + tx * 4];
            float4 av = *(const float4*)&As[k * STR + tx * 4];
            float xr[4] = {xv.x, xv.y, xv.z, xv.w};
            float pr[4] = {pv.x, pv.y, pv.z, pv.w};
            float ar[4] = {av.x, av.y, av.z, av.w};
            #pragma unroll
            for (int i = 0; i < 4; i++)
                #pragma unroll
                for (int j = 0; j < 4; j++) {
                    axp[i][j] = fmaf(xr[i], pr[j], axp[i][j]);
                    axa[i][j] = fmaf(xr[i], ar[j], axa[i][j]);
                }
        }
    }

    // ---- Epilogue: stats from global, fused approx hyperbolic math.
    float4 xx  = *(const float4*)&g_x2[n0 + ty * 4];
    float4 pp  = *(const float4*)&g_p2[c0 + tx * 4];
    float4 pv4 = *(const float4*)&g_pa[c0 + tx * 4];
    float4 iv  = *(const float4*)&g_ina[c0 + tx * 4];
    float4 wv4 = *(const float4*)&g_w2[c0 + tx * 4];
    float x2v[4]  = {xx.x, xx.y, xx.z, xx.w};
    float p2v[4]  = {pp.x, pp.y, pp.z, pp.w};
    float pav[4]  = {pv4.x, pv4.y, pv4.z, pv4.w};
    float inav[4] = {iv.x, iv.y, iv.z, iv.w};
    float wv[4]   = {wv4.x, wv4.y, wv4.z, wv4.w};
    float x2p1[4], bet[4], bet2[4];
    #pragma unroll
    for (int i = 0; i < 4; i++) x2p1[i] = 1.0f + x2v[i];
    #pragma unroll
    for (int j = 0; j < 4; j++) {
        bet[j]  = 1.0f - p2v[j];
        bet2[j] = bet[j] * bet[j];
    }

    #pragma unroll
    for (int i = 0; i < 4; i++) {
        const int n = n0 + ty * 4 + i;
        float res[4];
        #pragma unroll
        for (int j = 0; j < 4; j++) {
            float xp  = axp[i][j];                   // x.p
            float xa  = axa[i][j];                   // x.a
            float txy = -2.0f * xp;                  // 2*xy (xy = mp.x = -xp)
            float alpha = x2p1[i] + txy;             // 1 + 2xy + x2
            float den   = fmaf(p2v[j], x2v[i], 1.0f + txy);
            float s   = fmaf(alpha, fmaf(alpha, p2v[j], bet[j] * txy),
                             bet2[j] * x2v[i]);
            float num = fmaf(bet[j], xa, -alpha * pav[j]);   // b*xa - a*pa
            float d2ms = fmaf(den, den, -s);                 // den^2 - s
            float arg = 2.0f * den * num * inav[j] * fast_rcp(d2ms);
            float q   = arg + fast_sqrt(fmaf(arg, arg, 1.0f));
            res[j] = wv[j] * fast_lg2(q);            // 2*na*ln2 * log2(q)
        }
        float4 o = {res[0], res[1], res[2], res[3]};
        *(float4*)&out[(size_t)n * C_TOT + c0 + tx * 4] = o;
    }
}

extern "C" void kernel_launch(void* const* d_in, const int* in_sizes, int n_in,
                              void* d_out, int out_size) {
    const float* X = (const float*)d_in[0];   // output_before (N, D)
    const float* A = (const float*)d_in[1];   // a_mlr (C, D)
    const float* P = (const float*)d_in[2];   // p_mlr (C, D)
    float* out = (float*)d_out;               // (N, C)

    cudaFuncSetAttribute(hyp_mlr_kernel,
                         cudaFuncAttributeMaxDynamicSharedMemorySize,
                         SMEM_BYTES);

    stats_kernel<<<128, 256>>>(X, A, P);
    dim3 grid(C_TOT / BC, N_TOT / BN);        // (4, 64) = 256 blocks
    hyp_mlr_kernel<<<grid, 256, SMEM_BYTES>>>(X, A, P, out);
}

// round 8
// speedup vs baseline: 1.3056x; 1.0946x over previous
#include <cuda_runtime.h>
#include <math.h>

// Hyp-MLR: N=4096, C=256, D=128, CURV=1
// Single fused kernel: dual GEMM (X.P^T, X.A^T) with per-row/per-class stats
// (x2, p2, a2, p.a) computed from the fill registers (free under LDG latency),
// reduced in smem, consumed by the fused approx-asinh epilogue.
// GEMM: 64x64 tile, 256 threads, 4x4 dual microtile, KT=64 half-D phases,
// conflict-free transposing fill (warp spans 32 distinct rows per k).

#define N_TOT 4096
#define C_TOT 256
#define D_TOT 128
#define BN 64
#define BC 64
#define KT 64
#define STR 68             // k-major row stride in floats (272B, 16B-aligned)
#define TILE_FLOATS (KT * STR)                  // 4352
#define SMEM_FLOATS (3 * TILE_FLOATS + 4 * 256 + 5 * 64)
#define SMEM_BYTES (SMEM_FLOATS * 4)
#define LN2F 0.69314718055994530942f

__device__ __forceinline__ float fast_rcp(float x) {
    float y; asm("rcp.approx.f32 %0, %1;" : "=f"(y) : "f"(x)); return y;
}
__device__ __forceinline__ float fast_sqrt(float x) {
    float y; asm("sqrt.approx.f32 %0, %1;" : "=f"(y) : "f"(x)); return y;
}
__device__ __forceinline__ float fast_lg2(float x) {
    float y; asm("lg2.approx.f32 %0, %1;" : "=f"(y) : "f"(x)); return y;
}
__device__ __forceinline__ float dot4(float4 a, float4 b) {
    return a.x * b.x + a.y * b.y + a.z * b.z + a.w * b.w;
}

__global__ __launch_bounds__(256, 2) void hyp_mlr_kernel(
    const float* __restrict__ X,   // (N, D)
    const float* __restrict__ A,   // (C, D)
    const float* __restrict__ P,   // (C, D)
    float* __restrict__ out)       // (N, C)
{
    extern __shared__ float smem[];
    float* Xs = smem;                       // [KT][STR] k-major
    float* Ps = smem + TILE_FLOATS;
    float* As = smem + 2 * TILE_FLOATS;
    float* sc_x2 = smem + 3 * TILE_FLOATS;  // [4][64] slab partials
    float* sc_p2 = sc_x2 + 256;
    float* sc_a2 = sc_p2 + 256;
    float* sc_pa = sc_a2 + 256;
    float* sx2  = sc_pa + 256;              // [64] finals
    float* sp2  = sx2 + 64;
    float* spa  = sp2 + 64;
    float* sina = spa + 64;
    float* sw2  = sina + 64;

    const int tid = threadIdx.x;
    const int tx  = tid & 15;   // c dim
    const int ty  = tid >> 4;   // n dim
    const int n0  = blockIdx.y * BN;
    const int c0  = blockIdx.x * BC;

    // Fill mapping: warp spans 32 distinct rows at one k -> conflict-free STS.
    const int frow = tid & 63;          // 0..63
    const int fks  = (tid >> 6) * 16;   // k sub-slab start: 0,16,32,48

    float axp[4][4] = {};   // x.p partials
    float axa[4][4] = {};   // x.a partials
    float x2p = 0.f, p2p = 0.f, a2p = 0.f, pap = 0.f;   // stats partials

    #pragma unroll
    for (int ph = 0; ph < 2; ph++) {
        if (ph) __syncthreads();          // protect smem reuse across phases
        const int kb = ph * KT;
        // Per array: 4 LDG.128 (row-strided; L2-resident) + 16 scalar STS.
        const float* xg = &X[(size_t)(n0 + frow) * D_TOT + kb + fks];
        const float* pg = &P[(size_t)(c0 + frow) * D_TOT + kb + fks];
        const float* ag = &A[(size_t)(c0 + frow) * D_TOT + kb + fks];
        #pragma unroll
        for (int q = 0; q < 4; q++) {
            float4 xv = *(const float4*)&xg[q * 4];
            float4 pv = *(const float4*)&pg[q * 4];
            float4 av = *(const float4*)&ag[q * 4];
            // stats on in-flight data (hidden under LDG latency)
            x2p += dot4(xv, xv);
            p2p += dot4(pv, pv);
            a2p += dot4(av, av);
            pap += dot4(pv, av);
            int k = fks + q * 4;
            Xs[(k + 0) * STR + frow] = xv.x;
            Xs[(k + 1) * STR + frow] = xv.y;
            Xs[(k + 2) * STR + frow] = xv.z;
            Xs[(k + 3) * STR + frow] = xv.w;
            Ps[(k + 0) * STR + frow] = pv.x;
            Ps[(k + 1) * STR + frow] = pv.y;
            Ps[(k + 2) * STR + frow] = pv.z;
            Ps[(k + 3) * STR + frow] = pv.w;
            As[(k + 0) * STR + frow] = av.x;
            As[(k + 1) * STR + frow] = av.y;
            As[(k + 2) * STR + frow] = av.z;
            As[(k + 3) * STR + frow] = av.w;
        }
        __syncthreads();

        #pragma unroll 4
        for (int k = 0; k < KT; k++) {
            float4 xv = *(const float4*)&Xs[k * STR + ty * 4];
            float4 pv = *(const float4*)&Ps[k * STR + tx * 4];
            float4 av = *(const float4*)&As[k * STR + tx * 4];
            float xr[4] = {xv.x, xv.y, xv.z, xv.w};
            float pr[4] = {pv.x, pv.y, pv.z, pv.w};
            float ar[4] = {av.x, av.y, av.z, av.w};
            #pragma unroll
            for (int i = 0; i < 4; i++)
                #pragma unroll
                for (int j = 0; j < 4; j++) {
                    axp[i][j] = fmaf(xr[i], pr[j], axp[i][j]);
                    axa[i][j] = fmaf(xr[i], ar[j], axa[i][j]);
                }
        }
    }

    // ---- Stats reduction: 4 k-slab partials per row -> finals in smem.
    {
        const int slab = tid >> 6;
        sc_x2[slab * 64 + frow] = x2p;
        sc_p2[slab * 64 + frow] = p2p;
        sc_a2[slab * 64 + frow] = a2p;
        sc_pa[slab * 64 + frow] = pap;
    }
    __syncthreads();
    {
        const int r = tid & 63;
        if (tid < 64) {
            sx2[r] = sc_x2[r] + sc_x2[64 + r] + sc_x2[128 + r] + sc_x2[192 + r];
        } else if (tid < 128) {
            sp2[r] = sc_p2[r] + sc_p2[64 + r] + sc_p2[128 + r] + sc_p2[192 + r];
        } else if (tid < 192) {
            float a2 = sc_a2[r] + sc_a2[64 + r] + sc_a2[128 + r] + sc_a2[192 + r];
            float na = sqrtf(a2);
            sina[r] = fast_rcp(fmaxf(na, 1e-12f));
            sw2[r]  = 2.0f * na * LN2F;
        } else {
            spa[r] = sc_pa[r] + sc_pa[64 + r] + sc_pa[128 + r] + sc_pa[192 + r];
        }
    }
    __syncthreads();

    // ---- Epilogue: fused approx hyperbolic math, stats from smem.
    float x2v[4], x2p1[4];
    #pragma unroll
    for (int i = 0; i < 4; i++) {
        x2v[i]  = sx2[ty * 4 + i];
        x2p1[i] = 1.0f + x2v[i];
    }
    float p2v[4], bet[4], bet2[4], pav[4], inav[4], wv[4];
    #pragma unroll
    for (int j = 0; j < 4; j++) {
        p2v[j]  = sp2[tx * 4 + j];
        bet[j]  = 1.0f - p2v[j];
        bet2[j] = bet[j] * bet[j];
        pav[j]  = spa[tx * 4 + j];
        inav[j] = sina[tx * 4 + j];
        wv[j]   = sw2[tx * 4 + j];
    }

    #pragma unroll
    for (int i = 0; i < 4; i++) {
        const int n = n0 + ty * 4 + i;
        float res[4];
        #pragma unroll
        for (int j = 0; j < 4; j++) {
            float xp  = axp[i][j];                   // x.p
            float xa  = axa[i][j];                   // x.a
            float txy = -2.0f * xp;                  // 2*xy (xy = mp.x = -xp)
            float alpha = x2p1[i] + txy;             // 1 + 2xy + x2
            float den   = fmaf(p2v[j], x2v[i], 1.0f + txy);
            // s = ||res||^2 * den^2 = a^2 p2 + a*b*2xy + b^2 x2
            float s   = fmaf(alpha, fmaf(alpha, p2v[j], bet[j] * txy),
                             bet2[j] * x2v[i]);
            float num = fmaf(bet[j], xa, -alpha * pav[j]);   // b*xa - a*pa
            float d2ms = fmaf(den, den, -s);                 // den^2 - s
            // dot*lam = 2*den*num / (na * (den^2 - s))
            float arg = 2.0f * den * num * inav[j] * fast_rcp(d2ms);
            float q   = arg + fast_sqrt(fmaf(arg, arg, 1.0f));
            res[j] = wv[j] * fast_lg2(q);            // 2*na*ln2 * log2(q)
        }
        float4 o = {res[0], res[1], res[2], res[3]};
        *(float4*)&out[(size_t)n * C_TOT + c0 + tx * 4] = o;
    }
}

extern "C" void kernel_launch(void* const* d_in, const int* in_sizes, int n_in,
                              void* d_out, int out_size) {
    const float* X = (const float*)d_in[0];   // output_before (N, D)
    const float* A = (const float*)d_in[1];   // a_mlr (C, D)
    const float* P = (const float*)d_in[2];   // p_mlr (C, D)
    float* out = (float*)d_out;               // (N, C)

    cudaFuncSetAttribute(hyp_mlr_kernel,
                         cudaFuncAttributeMaxDynamicSharedMemorySize,
                         SMEM_BYTES);

    dim3 grid(C_TOT / BC, N_TOT / BN);        // (4, 64) = 256 blocks
    hyp_mlr_kernel<<<grid, 256, SMEM_BYTES>>>(X, A, P, out);
}